// round 11
// baseline (speedup 1.0000x reference)
#include <cuda_runtime.h>
#include <math.h>

#define Bb 8
#define Ss 4096
#define Dd 1024
#define Nn 16
#define ROWS (Bb * Ss) /* 32768 */

// Scratch (no cudaMalloc allowed)
__device__ float g_lam[ROWS * Nn];
__device__ float g_bx [ROWS * Nn];
__device__ float g_hs [ROWS * Nn];
__device__ float g_sqp[ROWS * 16];  // per-(row, bn*2 + warp_n) partial y^2

// Fast sigmoid: MUFU.EX2-based exp + MUFU.RCP divide. abs err ~1e-6,
// 3 orders below the tf32 GEMM error budget (~4e-4).
__device__ __forceinline__ float fsigmoid(float z) {
    return __fdividef(1.f, 1.f + __expf(-z));
}

// ---------------------------------------------------------------------------
// Kernel 1: lam = sigmoid(x @ W_lambda^T + b_lambda), Bx = x @ W_B^T
// 2048 blocks x 256 threads; each block: 16 rows x 32 outputs.
// ---------------------------------------------------------------------------
__global__ __launch_bounds__(256) void proj_kernel(
    const float* __restrict__ x,
    const float* __restrict__ Wl,
    const float* __restrict__ bl,
    const float* __restrict__ Wb)
{
    __shared__ float Xs[16][65];
    __shared__ float Ws[32][65];
    const int tid  = threadIdx.x;
    const int row0 = blockIdx.x * 16;
    const int tr = tid & 15;
    const int to = tid >> 4;
    float acc0 = 0.f, acc1 = 0.f;

    for (int k0 = 0; k0 < Dd; k0 += 64) {
        for (int i = tid; i < 16 * 64; i += 256) {
            int r = i >> 6, c = i & 63;
            Xs[r][c] = x[(size_t)(row0 + r) * Dd + k0 + c];
        }
        for (int i = tid; i < 32 * 64; i += 256) {
            int r = i >> 6, c = i & 63;
            const float* w = (r < 16) ? (Wl + (size_t)r * Dd)
                                      : (Wb + (size_t)(r - 16) * Dd);
            Ws[r][c] = w[k0 + c];
        }
        __syncthreads();
        #pragma unroll
        for (int c = 0; c < 64; c++) {
            float xv = Xs[tr][c];
            acc0 = fmaf(xv, Ws[to][c],      acc0);
            acc1 = fmaf(xv, Ws[to + 16][c], acc1);
        }
        __syncthreads();
    }
    const int row = row0 + tr;
    g_lam[row * Nn + to] = fsigmoid(acc0 + bl[to]);
    g_bx [row * Nn + to] = acc1;
}

// ---------------------------------------------------------------------------
// Kernel 2: associative scan h_t = lam_t * h_{t-1} + Bx_t over S=4096.
// 128 blocks (one per (b,n) chain) x 256 threads, 16 timesteps per thread.
// Chunk composition: applying (l,b) to state (L,Bc): L' = l*L, Bc' = l*Bc + b.
// ---------------------------------------------------------------------------
__global__ __launch_bounds__(256) void scan_kernel()
{
    __shared__ float Ls[256];
    __shared__ float Bcs[256];
    const int tid = threadIdx.x;
    const int b = blockIdx.x >> 4;
    const int n = blockIdx.x & 15;
    const size_t base = ((size_t)b * Ss) * Nn + n;
    const int s0 = tid * 16;

    float L = 1.f, Bc = 0.f;
    #pragma unroll
    for (int k = 0; k < 16; k++) {
        size_t idx = base + (size_t)(s0 + k) * Nn;
        float l  = g_lam[idx];
        float bv = g_bx[idx];
        Bc = fmaf(l, Bc, bv);
        L  = l * L;
    }
    Ls[tid] = L; Bcs[tid] = Bc;
    __syncthreads();

    if (tid == 0) {
        // exclusive serial scan of 256 chunk summaries (cheap, deterministic)
        float cL = 1.f, cB = 0.f;
        for (int i = 0; i < 256; i++) {
            float tl = Ls[i], tb = Bcs[i];
            Ls[i] = cL; Bcs[i] = cB;
            float nB = fmaf(tl, cB, tb);
            cL = tl * cL;
            cB = nB;
        }
    }
    __syncthreads();

    float h = Bcs[tid];  // h0 = 0 -> state entering this chunk is the prefix Bc
    #pragma unroll
    for (int k = 0; k < 16; k++) {
        size_t idx = base + (size_t)(s0 + k) * Nn;
        h = fmaf(g_lam[idx], h, g_bx[idx]);
        g_hs[idx] = h;
    }
}

// ---------------------------------------------------------------------------
// Kernel 3: gate GEMM via tf32 mma.sync.m16n8k8, fused epilogue.
// 128x128 CTA tile, BK=16, 128 threads = 4 warps (2 warp_m x 2 warp_n),
// warp tile 64x64 -> LDS bytes per kk-step: 4*(64+64)*8*4 = 16KB (vs 24KB
// for 8 warps of 64x32). Per-mma fragment maps identical to the audited
// 8-warp version; only warp-grid constants and loop bounds differ.
// Double-buffered smem, one barrier per K-tile. Row stride 20 -> fragment
// LDS (addr 20q+r) covers all 32 banks, conflict-free.
// Audits: regs ~212 < 255 (lb 128,2); smem 40KB*2=80KB; 8 warps/SM.
// ---------------------------------------------------------------------------
__device__ __forceinline__ unsigned f2tf(float f) {
    unsigned u;
    asm("cvt.rna.tf32.f32 %0, %1;" : "=r"(u) : "f"(f));
    return u;
}

__device__ __forceinline__ uint4 f2tf4(float4 v) {
    uint4 u;
    u.x = f2tf(v.x); u.y = f2tf(v.y); u.z = f2tf(v.z); u.w = f2tf(v.w);
    return u;
}

__device__ __forceinline__ void mma_tf32(float d[4], const unsigned a[4],
                                         const unsigned b[2]) {
    asm volatile(
        "mma.sync.aligned.m16n8k8.row.col.f32.tf32.tf32.f32 "
        "{%0,%1,%2,%3}, {%4,%5,%6,%7}, {%8,%9}, {%0,%1,%2,%3};"
        : "+f"(d[0]), "+f"(d[1]), "+f"(d[2]), "+f"(d[3])
        : "r"(a[0]), "r"(a[1]), "r"(a[2]), "r"(a[3]), "r"(b[0]), "r"(b[1]));
}

__global__ __launch_bounds__(128, 2) void gate_kernel(
    const float* __restrict__ x,
    const float* __restrict__ Wg,
    const float* __restrict__ Wc,
    float* __restrict__ out)
{
    __shared__ __align__(16) unsigned As[2][128][20];  // [buf][row m][k]
    __shared__ __align__(16) unsigned Bs[2][128][20];  // [buf][row n][k]

    const int tid = threadIdx.x;
    const int bn = blockIdx.x;            // 0..7   (e direction)
    const int bm = blockIdx.y;            // 0..255 (row direction)
    const int row0 = bm * 128;
    const int e0   = bn * 128;

    const int lane = tid & 31;
    const int wid  = tid >> 5;            // 0..3
    const int warp_m = wid >> 1;          // 0..1 -> 64 rows
    const int warp_n = wid & 1;           // 0..1 -> 64 cols
    const int q = lane >> 2;              // 0..7
    const int r = lane & 3;               // 0..3

    const int lr = tid >> 2;              // 0..31 (load row base)
    const int lc = (tid & 3) * 4;         // 0,4,8,12 (load k offset)

    float acc[4][8][4];
    #pragma unroll
    for (int i = 0; i < 4; i++)
        #pragma unroll
        for (int j = 0; j < 8; j++)
            #pragma unroll
            for (int t = 0; t < 4; t++) acc[i][j][t] = 0.f;

    const float* Aptr = x  + (size_t)(row0 + lr) * Dd + lc;
    const float* Bptr = Wg + (size_t)(e0   + lr) * Dd + lc;

    // Prologue: fetch K-tile 0 (4 row-chunks of 32 for each of A, B)
    float4 a0 = *(const float4*)(Aptr);
    float4 a1 = *(const float4*)(Aptr + (size_t)32 * Dd);
    float4 a2 = *(const float4*)(Aptr + (size_t)64 * Dd);
    float4 a3 = *(const float4*)(Aptr + (size_t)96 * Dd);
    float4 b0 = *(const float4*)(Bptr);
    float4 b1 = *(const float4*)(Bptr + (size_t)32 * Dd);
    float4 b2 = *(const float4*)(Bptr + (size_t)64 * Dd);
    float4 b3 = *(const float4*)(Bptr + (size_t)96 * Dd);

    int buf = 0;
    for (int k0 = 0; k0 < Dd; k0 += 16) {
        // Store (tf32-converted, STS.128) into buffer `buf`
        *(uint4*)&As[buf][lr     ][lc] = f2tf4(a0);
        *(uint4*)&As[buf][lr + 32][lc] = f2tf4(a1);
        *(uint4*)&As[buf][lr + 64][lc] = f2tf4(a2);
        *(uint4*)&As[buf][lr + 96][lc] = f2tf4(a3);
        *(uint4*)&Bs[buf][lr     ][lc] = f2tf4(b0);
        *(uint4*)&Bs[buf][lr + 32][lc] = f2tf4(b1);
        *(uint4*)&Bs[buf][lr + 64][lc] = f2tf4(b2);
        *(uint4*)&Bs[buf][lr + 96][lc] = f2tf4(b3);
        __syncthreads();

        // Branch-free prefetch of next K-tile (final iter re-reads the last
        // tile; registers are dead since the loop exits before next store).
        {
            int kn = k0 + 16 < Dd ? k0 + 16 : k0;  // uniform SEL, no branch
            a0 = *(const float4*)(Aptr + kn);
            a1 = *(const float4*)(Aptr + (size_t)32 * Dd + kn);
            a2 = *(const float4*)(Aptr + (size_t)64 * Dd + kn);
            a3 = *(const float4*)(Aptr + (size_t)96 * Dd + kn);
            b0 = *(const float4*)(Bptr + kn);
            b1 = *(const float4*)(Bptr + (size_t)32 * Dd + kn);
            b2 = *(const float4*)(Bptr + (size_t)64 * Dd + kn);
            b3 = *(const float4*)(Bptr + (size_t)96 * Dd + kn);
        }

        #pragma unroll
        for (int kk = 0; kk < 16; kk += 8) {
            unsigned af[4][4];
            #pragma unroll
            for (int i = 0; i < 4; i++) {
                int m0 = warp_m * 64 + i * 16 + q;
                af[i][0] = As[buf][m0    ][kk + r];
                af[i][1] = As[buf][m0 + 8][kk + r];
                af[i][2] = As[buf][m0    ][kk + 4 + r];
                af[i][3] = As[buf][m0 + 8][kk + 4 + r];
            }
            unsigned bf[8][2];
            #pragma unroll
            for (int j = 0; j < 8; j++) {
                int n0 = warp_n * 64 + j * 8 + q;
                bf[j][0] = Bs[buf][n0][kk + r];
                bf[j][1] = Bs[buf][n0][kk + 4 + r];
            }
            #pragma unroll
            for (int i = 0; i < 4; i++)
                #pragma unroll
                for (int j = 0; j < 8; j++)
                    mma_tf32(acc[i][j], af[i], bf[j]);
        }
        buf ^= 1;
        // Single barrier per tile: stores(i+2) to this buf only run after
        // sync(i+1), reached only after each warp's compute(i) reads of it.
    }
    __syncthreads();

    // Epilogue tiles alias GEMM smem: hs[row0..+128,16], W_C[e0..+128,16]
    float* hsS = (float*)&As[0][0][0];            // 128*17 floats
    float* wcS = (float*)&As[0][0][0] + 2176;     // 128*17 floats
    for (int i = tid; i < 128 * 16; i += 128) {
        int rr = i >> 4, c = i & 15;
        hsS[rr * 17 + c] = g_hs[(size_t)(row0 + rr) * Nn + c];
        wcS[rr * 17 + c] = Wc[(size_t)(e0 + rr) * Nn + c];
    }
    __syncthreads();

    // Fragment ownership (unchanged per-mma map): elem (i,h,j,c) ->
    // m = warp_m*64 + i*16 + q + 8h, n = warp_n*64 + j*8 + 2r + c,
    // acc reg = 2h + c.
    #pragma unroll
    for (int i = 0; i < 4; i++) {
        #pragma unroll
        for (int h = 0; h < 2; h++) {
            int m   = warp_m * 64 + i * 16 + q + 8 * h;
            int row = row0 + m;
            float hv[16];
            #pragma unroll
            for (int t = 0; t < 16; t++) hv[t] = hsS[m * 17 + t];

            float ssum = 0.f;
            #pragma unroll
            for (int j = 0; j < 8; j++) {
                int n = warp_n * 64 + j * 8 + 2 * r;
                float v2[2];
                #pragma unroll
                for (int c = 0; c < 2; c++) {
                    float yl = 0.f;
                    #pragma unroll
                    for (int t = 0; t < 16; t++)
                        yl = fmaf(hv[t], wcS[(n + c) * 17 + t], yl);
                    float g = fsigmoid(acc[i][j][2 * h + c]);
                    float v = g * yl;
                    ssum = fmaf(v, v, ssum);
                    v2[c] = v;
                }
                *(float2*)(out + (size_t)row * Dd + e0 + n) =
                    make_float2(v2[0], v2[1]);
            }
            // Reduce across the 4 lanes (r=0..3, consecutive) sharing this row
            ssum += __shfl_down_sync(0xffffffffu, ssum, 2, 4);
            ssum += __shfl_down_sync(0xffffffffu, ssum, 1, 4);
            if (r == 0)
                g_sqp[(size_t)row * 16 + bn * 2 + warp_n] = ssum;
        }
    }
}

// ---------------------------------------------------------------------------
// Kernel 4: RMSNorm finalize. One block per row; the 16 partials are
// reduced once (width-16 shuffle), then all threads scale in place.
// ---------------------------------------------------------------------------
__global__ __launch_bounds__(256) void norm_kernel(
    float* __restrict__ out, const float* __restrict__ rmsw)
{
    __shared__ float s_scale;
    const int row = blockIdx.x;
    const int tid = threadIdx.x;

    if (tid < 16) {
        float v = g_sqp[(size_t)row * 16 + tid];
        #pragma unroll
        for (int off = 8; off > 0; off >>= 1)
            v += __shfl_down_sync(0x0000ffffu, v, off, 16);
        if (tid == 0)
            s_scale = rsqrtf(v * (1.0f / Dd) + 1e-6f);
    }
    __syncthreads();
    float scale = s_scale;

    float4* o = (float4*)(out + (size_t)row * Dd);
    const float4* rw = (const float4*)rmsw;
    float4 v = o[tid];
    float4 w = rw[tid];
    v.x *= scale * w.x;
    v.y *= scale * w.y;
    v.z *= scale * w.z;
    v.w *= scale * w.w;
    o[tid] = v;
}

// ---------------------------------------------------------------------------
extern "C" void kernel_launch(void* const* d_in, const int* in_sizes, int n_in,
                              void* d_out, int out_size)
{
    const float* x  = (const float*)d_in[0];
    const float* Wl = (const float*)d_in[1];
    const float* bl = (const float*)d_in[2];
    const float* Wb = (const float*)d_in[3];
    const float* Wc = (const float*)d_in[4];
    const float* Wg = (const float*)d_in[5];
    const float* rw = (const float*)d_in[6];
    float* out = (float*)d_out;

    proj_kernel<<<ROWS / 16, 256>>>(x, Wl, bl, Wb);
    scan_kernel<<<Bb * Nn, 256>>>();
    dim3 g(Dd / 128, ROWS / 128);
    gate_kernel<<<g, 128>>>(x, Wg, Wc, out);
    norm_kernel<<<ROWS, 256>>>(out, rw);
}

// round 14
// speedup vs baseline: 1.0196x; 1.0196x over previous
#include <cuda_runtime.h>
#include <math.h>

#define Bb 8
#define Ss 4096
#define Dd 1024
#define Nn 16
#define ROWS (Bb * Ss) /* 32768 */

// Scratch (no cudaMalloc allowed)
__device__ float g_lam[ROWS * Nn];
__device__ float g_bx [ROWS * Nn];
__device__ float g_hs [ROWS * Nn];
__device__ float g_sqp[ROWS * 32];  // per-(row, bn*4 + warp_n) partial y^2

// Fast sigmoid: MUFU.EX2-based exp + MUFU.RCP divide. abs err ~1e-6.
__device__ __forceinline__ float fsigmoid(float z) {
    return __fdividef(1.f, 1.f + __expf(-z));
}

// ---------------------------------------------------------------------------
// Kernel 1: lam = sigmoid(x @ W_lambda^T + b_lambda), Bx = x @ W_B^T
// ---------------------------------------------------------------------------
__global__ __launch_bounds__(256) void proj_kernel(
    const float* __restrict__ x,
    const float* __restrict__ Wl,
    const float* __restrict__ bl,
    const float* __restrict__ Wb)
{
    __shared__ float Xs[16][65];
    __shared__ float Ws[32][65];
    const int tid  = threadIdx.x;
    const int row0 = blockIdx.x * 16;
    const int tr = tid & 15;
    const int to = tid >> 4;
    float acc0 = 0.f, acc1 = 0.f;

    for (int k0 = 0; k0 < Dd; k0 += 64) {
        for (int i = tid; i < 16 * 64; i += 256) {
            int r = i >> 6, c = i & 63;
            Xs[r][c] = x[(size_t)(row0 + r) * Dd + k0 + c];
        }
        for (int i = tid; i < 32 * 64; i += 256) {
            int r = i >> 6, c = i & 63;
            const float* w = (r < 16) ? (Wl + (size_t)r * Dd)
                                      : (Wb + (size_t)(r - 16) * Dd);
            Ws[r][c] = w[k0 + c];
        }
        __syncthreads();
        #pragma unroll
        for (int c = 0; c < 64; c++) {
            float xv = Xs[tr][c];
            acc0 = fmaf(xv, Ws[to][c],      acc0);
            acc1 = fmaf(xv, Ws[to + 16][c], acc1);
        }
        __syncthreads();
    }
    const int row = row0 + tr;
    g_lam[row * Nn + to] = fsigmoid(acc0 + bl[to]);
    g_bx [row * Nn + to] = acc1;
}

// ---------------------------------------------------------------------------
// Kernel 2: associative scan h_t = lam_t * h_{t-1} + Bx_t over S=4096.
// ---------------------------------------------------------------------------
__global__ __launch_bounds__(256) void scan_kernel()
{
    __shared__ float Ls[256];
    __shared__ float Bcs[256];
    const int tid = threadIdx.x;
    const int b = blockIdx.x >> 4;
    const int n = blockIdx.x & 15;
    const size_t base = ((size_t)b * Ss) * Nn + n;
    const int s0 = tid * 16;

    float L = 1.f, Bc = 0.f;
    #pragma unroll
    for (int k = 0; k < 16; k++) {
        size_t idx = base + (size_t)(s0 + k) * Nn;
        float l  = g_lam[idx];
        float bv = g_bx[idx];
        Bc = fmaf(l, Bc, bv);
        L  = l * L;
    }
    Ls[tid] = L; Bcs[tid] = Bc;
    __syncthreads();

    if (tid == 0) {
        float cL = 1.f, cB = 0.f;
        for (int i = 0; i < 256; i++) {
            float tl = Ls[i], tb = Bcs[i];
            Ls[i] = cL; Bcs[i] = cB;
            float nB = fmaf(tl, cB, tb);
            cL = tl * cL;
            cB = nB;
        }
    }
    __syncthreads();

    float h = Bcs[tid];
    #pragma unroll
    for (int k = 0; k < 16; k++) {
        size_t idx = base + (size_t)(s0 + k) * Nn;
        h = fmaf(g_lam[idx], h, g_bx[idx]);
        g_hs[idx] = h;
    }
}

// ---------------------------------------------------------------------------
// Kernel 3: gate GEMM via tf32 mma.sync.m16n8k8, fused epilogue.
// GEOMETRY REVERTED to the audited 8-warp form after Round-11 measurement:
// gate ~835us at 2 warps/SMSP indicates latency exposure, not crossbar
// bytes (byte bound is ~123us). 128x128 CTA tile, BK=16, 256 threads =
// 8 warps (2 warp_m x 4 warp_n), warp tile 64x32, acc=64 regs/thread ->
// 2 CTA/SM = 16 warps/SM = 4/SMSP (2x latency hiding vs Round 10/11).
// Double-buffered smem, one barrier per K-tile. Row stride 20 ->
// conflict-free fragment LDS. STS.128 tf32-converted fills.
// ---------------------------------------------------------------------------
__device__ __forceinline__ unsigned f2tf(float f) {
    unsigned u;
    asm("cvt.rna.tf32.f32 %0, %1;" : "=r"(u) : "f"(f));
    return u;
}

__device__ __forceinline__ uint4 f2tf4(float4 v) {
    uint4 u;
    u.x = f2tf(v.x); u.y = f2tf(v.y); u.z = f2tf(v.z); u.w = f2tf(v.w);
    return u;
}

__device__ __forceinline__ void mma_tf32(float d[4], const unsigned a[4],
                                         const unsigned b[2]) {
    asm volatile(
        "mma.sync.aligned.m16n8k8.row.col.f32.tf32.tf32.f32 "
        "{%0,%1,%2,%3}, {%4,%5,%6,%7}, {%8,%9}, {%0,%1,%2,%3};"
        : "+f"(d[0]), "+f"(d[1]), "+f"(d[2]), "+f"(d[3])
        : "r"(a[0]), "r"(a[1]), "r"(a[2]), "r"(a[3]), "r"(b[0]), "r"(b[1]));
}

__global__ __launch_bounds__(256, 2) void gate_kernel(
    const float* __restrict__ x,
    const float* __restrict__ Wg,
    const float* __restrict__ Wc,
    float* __restrict__ out)
{
    __shared__ __align__(16) unsigned As[2][128][20];  // [buf][row m][k]
    __shared__ __align__(16) unsigned Bs[2][128][20];  // [buf][row n][k]

    const int tid = threadIdx.x;
    const int bn = blockIdx.x;            // 0..7   (e direction)
    const int bm = blockIdx.y;            // 0..255 (row direction)
    const int row0 = bm * 128;
    const int e0   = bn * 128;

    const int lane = tid & 31;
    const int wid  = tid >> 5;
    const int warp_m = wid >> 2;          // 0..1 -> 64 rows
    const int warp_n = wid & 3;           // 0..3 -> 32 cols
    const int q = lane >> 2;              // 0..7
    const int r = lane & 3;               // 0..3

    const int ar = tid >> 2;              // 0..63 (load row)
    const int ac = (tid & 3) * 4;         // 0,4,8,12 (load k offset)

    float acc[4][4][4];
    #pragma unroll
    for (int i = 0; i < 4; i++)
        #pragma unroll
        for (int j = 0; j < 4; j++)
            #pragma unroll
            for (int t = 0; t < 4; t++) acc[i][j][t] = 0.f;

    const float* Aptr = x  + (size_t)(row0 + ar) * Dd + ac;
    const float* Bptr = Wg + (size_t)(e0   + ar) * Dd + ac;

    // Prologue: fetch K-tile 0
    float4 a0 = *(const float4*)(Aptr);
    float4 a1 = *(const float4*)(Aptr + (size_t)64 * Dd);
    float4 b0 = *(const float4*)(Bptr);
    float4 b1 = *(const float4*)(Bptr + (size_t)64 * Dd);

    int buf = 0;
    for (int k0 = 0; k0 < Dd; k0 += 16) {
        *(uint4*)&As[buf][ar     ][ac] = f2tf4(a0);
        *(uint4*)&As[buf][ar + 64][ac] = f2tf4(a1);
        *(uint4*)&Bs[buf][ar     ][ac] = f2tf4(b0);
        *(uint4*)&Bs[buf][ar + 64][ac] = f2tf4(b1);
        __syncthreads();

        // Branch-free prefetch of next K-tile (final iter re-reads last
        // tile; those regs are dead — loop exits before the next store).
        {
            int kn = k0 + 16 < Dd ? k0 + 16 : k0;
            a0 = *(const float4*)(Aptr + kn);
            a1 = *(const float4*)(Aptr + (size_t)64 * Dd + kn);
            b0 = *(const float4*)(Bptr + kn);
            b1 = *(const float4*)(Bptr + (size_t)64 * Dd + kn);
        }

        #pragma unroll
        for (int kk = 0; kk < 16; kk += 8) {
            unsigned af[4][4];
            #pragma unroll
            for (int i = 0; i < 4; i++) {
                int m0 = warp_m * 64 + i * 16 + q;
                af[i][0] = As[buf][m0    ][kk + r];
                af[i][1] = As[buf][m0 + 8][kk + r];
                af[i][2] = As[buf][m0    ][kk + 4 + r];
                af[i][3] = As[buf][m0 + 8][kk + 4 + r];
            }
            unsigned bf[4][2];
            #pragma unroll
            for (int j = 0; j < 4; j++) {
                int n0 = warp_n * 32 + j * 8 + q;
                bf[j][0] = Bs[buf][n0][kk + r];
                bf[j][1] = Bs[buf][n0][kk + 4 + r];
            }
            #pragma unroll
            for (int i = 0; i < 4; i++)
                #pragma unroll
                for (int j = 0; j < 4; j++)
                    mma_tf32(acc[i][j], af[i], bf[j]);
        }
        buf ^= 1;
        // Single barrier per tile: stores(i+2) to this buf only run after
        // sync(i+1), reached only after each warp's compute(i) reads of it.
    }
    __syncthreads();

    // Epilogue tiles alias GEMM smem: hs[row0..+128,16], W_C[e0..+128,16]
    float* hsS = (float*)&As[0][0][0];            // 128*17 floats
    float* wcS = (float*)&As[0][0][0] + 2176;     // 128*17 floats
    for (int i = tid; i < 128 * 16; i += 256) {
        int rr = i >> 4, c = i & 15;
        hsS[rr * 17 + c] = g_hs[(size_t)(row0 + rr) * Nn + c];
        wcS[rr * 17 + c] = Wc[(size_t)(e0 + rr) * Nn + c];
    }
    __syncthreads();

    // Fragment ownership: elem (i,h,j,c) -> m = warp_m*64 + i*16 + q + 8h,
    // n = warp_n*32 + j*8 + 2r + c, acc reg = 2h + c.
    #pragma unroll
    for (int i = 0; i < 4; i++) {
        #pragma unroll
        for (int h = 0; h < 2; h++) {
            int m   = warp_m * 64 + i * 16 + q + 8 * h;
            int row = row0 + m;
            float hv[16];
            #pragma unroll
            for (int t = 0; t < 16; t++) hv[t] = hsS[m * 17 + t];

            float ssum = 0.f;
            #pragma unroll
            for (int j = 0; j < 4; j++) {
                int n = warp_n * 32 + j * 8 + 2 * r;
                float v2[2];
                #pragma unroll
                for (int c = 0; c < 2; c++) {
                    float yl = 0.f;
                    #pragma unroll
                    for (int t = 0; t < 16; t++)
                        yl = fmaf(hv[t], wcS[(n + c) * 17 + t], yl);
                    float g = fsigmoid(acc[i][j][2 * h + c]);
                    float v = g * yl;
                    ssum = fmaf(v, v, ssum);
                    v2[c] = v;
                }
                *(float2*)(out + (size_t)row * Dd + e0 + n) =
                    make_float2(v2[0], v2[1]);
            }
            ssum += __shfl_down_sync(0xffffffffu, ssum, 2, 4);
            ssum += __shfl_down_sync(0xffffffffu, ssum, 1, 4);
            if (r == 0)
                g_sqp[(size_t)row * 32 + bn * 4 + warp_n] = ssum;
        }
    }
}

// ---------------------------------------------------------------------------
// Kernel 4: RMSNorm finalize. One block per row; warp 0 reduces the 32
// partials once, then all threads scale in place. (49us measured — near
// the DRAM floor for its 268MB of traffic; leave alone.)
// ---------------------------------------------------------------------------
__global__ __launch_bounds__(256) void norm_kernel(
    float* __restrict__ out, const float* __restrict__ rmsw)
{
    __shared__ float s_scale;
    const int row = blockIdx.x;
    const int tid = threadIdx.x;

    if (tid < 32) {
        float v = g_sqp[(size_t)row * 32 + tid];
        #pragma unroll
        for (int off = 16; off > 0; off >>= 1)
            v += __shfl_down_sync(0xffffffffu, v, off);
        if (tid == 0)
            s_scale = rsqrtf(v * (1.0f / Dd) + 1e-6f);
    }
    __syncthreads();
    float scale = s_scale;

    float4* o = (float4*)(out + (size_t)row * Dd);
    const float4* rw = (const float4*)rmsw;
    float4 v = o[tid];
    float4 w = rw[tid];
    v.x *= scale * w.x;
    v.y *= scale * w.y;
    v.z *= scale * w.z;
    v.w *= scale * w.w;
    o[tid] = v;
}

// ---------------------------------------------------------------------------
extern "C" void kernel_launch(void* const* d_in, const int* in_sizes, int n_in,
                              void* d_out, int out_size)
{
    const float* x  = (const float*)d_in[0];
    const float* Wl = (const float*)d_in[1];
    const float* bl = (const float*)d_in[2];
    const float* Wb = (const float*)d_in[3];
    const float* Wc = (const float*)d_in[4];
    const float* Wg = (const float*)d_in[5];
    const float* rw = (const float*)d_in[6];
    float* out = (float*)d_out;

    proj_kernel<<<ROWS / 16, 256>>>(x, Wl, bl, Wb);
    scan_kernel<<<Bb * Nn, 256>>>();
    dim3 g(Dd / 128, ROWS / 128);
    gate_kernel<<<g, 256>>>(x, Wg, Wc, out);
    norm_kernel<<<ROWS, 256>>>(out, rw);
}